// round 15
// baseline (speedup 1.0000x reference)
#include <cuda_runtime.h>
#include <cuda_fp16.h>
#include <cstdint>

// Problem constants (fixed by the dataset)
#define MAXN 100000
#define MAXE 1600000
#define HDIM 128
#define NSCAN_BLOCKS ((MAXN + 1023) / 1024)

// ---------------- scratch (device globals; no runtime allocation) ----------
__device__ int      g_cnt[MAXN];
__device__ int      g_rowptr[MAXN + 1];
__device__ int2     g_edge[MAXE];            // packed (src, nrm-as-int) per edge
__device__ unsigned g_state[NSCAN_BLOCKS];   // lookback state: flag<<30 | value (UNSIGNED)
__device__ __half g_hb[(size_t)MAXN * HDIM]; // post-GEMM features (fp16)
__device__ __half g_xb[(size_t)MAXN * HDIM]; // aggregate out / GEMM in (fp16)
__device__ __half g_Wt[3 * HDIM * HDIM];     // W^T [n][k] fp16

// ---------------- helpers ----------------------------------------------------
__device__ __forceinline__ uint32_t smem_to_u32(const void* p) {
    uint32_t a;
    asm("{ .reg .u64 t; cvta.to.shared.u64 t, %1; cvt.u32.u64 %0, t; }"
        : "=r"(a) : "l"(p));
    return a;
}

__device__ __forceinline__ void ldsm_x4(uint32_t addr, uint32_t& r0, uint32_t& r1,
                                        uint32_t& r2, uint32_t& r3) {
    asm volatile("ldmatrix.sync.aligned.m8n8.x4.shared.b16 {%0,%1,%2,%3}, [%4];"
                 : "=r"(r0), "=r"(r1), "=r"(r2), "=r"(r3) : "r"(addr));
}

__device__ __forceinline__ void mma_fp16(float* c, uint32_t a0, uint32_t a1,
                                         uint32_t a2, uint32_t a3,
                                         uint32_t b0, uint32_t b1) {
    asm volatile(
        "mma.sync.aligned.m16n8k16.row.col.f32.f16.f16.f32 "
        "{%0,%1,%2,%3}, {%4,%5,%6,%7}, {%8,%9}, {%0,%1,%2,%3};"
        : "+f"(c[0]), "+f"(c[1]), "+f"(c[2]), "+f"(c[3])
        : "r"(a0), "r"(a1), "r"(a2), "r"(a3), "r"(b0), "r"(b1));
}

__device__ __forceinline__ void cp_async16(uint32_t smem_addr, const void* gptr) {
    asm volatile("cp.async.cg.shared.global [%0], [%1], 16;"
                 :: "r"(smem_addr), "l"(gptr));
}
#define CP_COMMIT()   asm volatile("cp.async.commit_group;" ::: "memory")
#define CP_WAIT_ALL() asm volatile("cp.async.wait_group 0;" ::: "memory")

__device__ __forceinline__ void acc8(float* a, uint4 u, float w) {
    float2 t;
    t = __half22float2(*(__half2*)&u.x); a[0] += t.x * w; a[1] += t.y * w;
    t = __half22float2(*(__half2*)&u.y); a[2] += t.x * w; a[3] += t.y * w;
    t = __half22float2(*(__half2*)&u.z); a[4] += t.x * w; a[5] += t.y * w;
    t = __half22float2(*(__half2*)&u.w); a[6] += t.x * w; a[7] += t.y * w;
}

// ---------------- CSR build -------------------------------------------------
__global__ void k_count(const int* __restrict__ dst, int e) {
    int i = blockIdx.x * blockDim.x + threadIdx.x;
    if (i < e) atomicAdd(&g_cnt[dst[i]], 1);
}

// single-pass exclusive scan of g_cnt -> g_rowptr via decoupled lookback.
// All NSCAN_BLOCKS (98) blocks are co-resident, so backward polling is safe.
// State is UNSIGNED: flag in bits [31:30], value in [29:0] (values < 2^30).
__global__ void k_scan(int n, int e) {
    int b = blockIdx.x;
    int i = b * 1024 + threadIdx.x;
    int v = (i < n) ? g_cnt[i] : 0;
    int lane = threadIdx.x & 31, wid = threadIdx.x >> 5;

    // local inclusive scan
    int x = v;
    #pragma unroll
    for (int o = 1; o < 32; o <<= 1) {
        int y = __shfl_up_sync(0xFFFFFFFFu, x, o);
        if (lane >= o) x += y;
    }
    __shared__ int ws[32];
    if (lane == 31) ws[wid] = x;
    __syncthreads();
    if (wid == 0) {
        int w = ws[lane];
        #pragma unroll
        for (int o = 1; o < 32; o <<= 1) {
            int y = __shfl_up_sync(0xFFFFFFFFu, w, o);
            if (lane >= o) w += y;
        }
        ws[lane] = w;
    }
    __syncthreads();
    int wpre = (wid > 0) ? ws[wid - 1] : 0;
    int incl = x + wpre;                     // inclusive within block
    __shared__ int s_total;
    if (threadIdx.x == 1023) {
        s_total = incl;
        __threadfence();
        atomicExch(&g_state[b], (1u << 30) | (unsigned)incl);   // publish aggregate
    }
    __syncthreads();
    int total = s_total;

    // lookback (thread 0): add aggregates backward; on an inclusive-prefix
    // entry (flag 2) add it and STOP.
    __shared__ int s_prefix;
    if (threadIdx.x == 0) {
        unsigned prefix = 0;
        for (int j = b - 1; j >= 0; j--) {
            unsigned s;
            do { s = atomicAdd(&g_state[j], 0u); } while ((s >> 30) == 0u);
            prefix += s & 0x3FFFFFFFu;
            if ((s >> 30) == 2u) break;       // inclusive prefix found -> done
        }
        s_prefix = (int)prefix;
    }
    __syncthreads();
    int prefix = s_prefix;
    if (threadIdx.x == 1023) {
        __threadfence();
        atomicExch(&g_state[b], (2u << 30) | (unsigned)(prefix + total));  // inclusive
    }

    if (i < n) g_rowptr[i] = prefix + incl - v;   // exclusive
    if (i == n) g_rowptr[n] = e;
}

// countdown-cursor fill; degree from rowptr diffs (+1 self-loop)
__global__ void k_fill(const int* __restrict__ src, const int* __restrict__ dst, int e) {
    int i = blockIdx.x * blockDim.x + threadIdx.x;
    if (i >= e) return;
    int d = dst[i], s = src[i];
    int rpd1 = g_rowptr[d + 1];
    int c = atomicAdd(&g_cnt[d], -1);
    int p = rpd1 - c;
    float degd = (float)(rpd1 - g_rowptr[d] + 1);
    float degs = (float)(g_rowptr[s + 1] - g_rowptr[s] + 1);
    float nrm = rsqrtf(degs * degd);
    g_edge[p] = make_int2(s, __float_as_int(nrm));
}

// ---------------- prep: W -> fp16 transposed AND x -> fp16 (merged) ---------
__global__ void k_prep(const float* __restrict__ W0, const float* __restrict__ W1,
                       const float* __restrict__ W2, const float* __restrict__ x,
                       int n) {
    int i = blockIdx.x * blockDim.x + threadIdx.x;
    const int WJOBS = 3 * HDIM * HDIM;
    if (i < WJOBS) {
        int l = i / (HDIM * HDIM);
        int r = i % (HDIM * HDIM);
        int nn = r / HDIM, kk = r % HDIM;
        const float* W = (l == 0) ? W0 : (l == 1) ? W1 : W2;
        g_Wt[l * HDIM * HDIM + nn * HDIM + kk] = __float2half_rn(W[kk * HDIM + nn]);
        return;
    }
    int j = i - WJOBS;                      // 8 x elements per job
    if (j >= n * (HDIM / 8)) return;
    const float4* p = (const float4*)x + (size_t)j * 2;
    float4 v0 = p[0], v1 = p[1];
    __half2 a = __floats2half2_rn(v0.x, v0.y);
    __half2 b = __floats2half2_rn(v0.z, v0.w);
    __half2 c = __floats2half2_rn(v1.x, v1.y);
    __half2 d = __floats2half2_rn(v1.z, v1.w);
    uint4 o;
    o.x = *(uint32_t*)&a; o.y = *(uint32_t*)&b;
    o.z = *(uint32_t*)&c; o.w = *(uint32_t*)&d;
    *((uint4*)g_xb + j) = o;
}

// ---------------- pipelined GEMM: Hb = Xb @ W + b ---------------------------
#define PADB 272
#define SM_W   0
#define SM_A0  (128 * PADB)
#define SM_A1  (2 * 128 * PADB)
#define SM_TOT (3 * 128 * PADB)   // 104448 -> 2 CTAs/SM

__device__ __forceinline__ void load_A_tile(char* smem, uint32_t sb, int abuf,
                                            int tile, int n, int tid) {
    uint32_t base = abuf ? SM_A1 : SM_A0;
    #pragma unroll
    for (int i = 0; i < 8; i++) {
        int gi = tid + i * 256;
        int r = gi >> 4, c16 = gi & 15;
        int row = tile * 128 + r;
        uint32_t dst = sb + base + r * PADB + c16 * 16;
        if (row < n) {
            cp_async16(dst, &g_xb[(size_t)row * HDIM + c16 * 8]);
        } else {
            *(uint4*)(smem + base + r * PADB + c16 * 16) = make_uint4(0, 0, 0, 0);
        }
    }
}

__global__ __launch_bounds__(256, 2) void k_gemm_pipe(
    const __half* __restrict__ Wt,
    const float* __restrict__ bias,
    int n, int ntiles, int gsz)
{
    extern __shared__ __align__(16) char smem[];
    uint32_t sb = smem_to_u32(smem);
    int tid = threadIdx.x;
    int lane = tid & 31, wid = tid >> 5;
    int wr = wid & 3;
    int wc = wid >> 2;

    int t0 = blockIdx.x;
    if (t0 >= ntiles) return;

    // prologue: W + first A tile via cp.async
    #pragma unroll
    for (int i = 0; i < 8; i++) {
        int gi = tid + i * 256;
        int r = gi >> 4, c16 = gi & 15;
        cp_async16(sb + SM_W + r * PADB + c16 * 16, &Wt[(size_t)r * HDIM + c16 * 8]);
    }
    load_A_tile(smem, sb, 0, t0, n, tid);
    CP_COMMIT();
    CP_WAIT_ALL();
    __syncthreads();

    int q = lane >> 3, rl = lane & 7;
    int rowA = wr * 32 + (q & 1) * 8 + rl;
    int colA = (q >> 1) * 16;
    int rowB = wc * 64 + (q >> 1) * 8 + rl;
    int colB = (q & 1) * 16;
    int g = lane >> 2, t4 = lane & 3;

    int abuf = 0;
    for (int tile = t0; tile < ntiles; tile += gsz) {
        int tnext = tile + gsz;
        if (tnext < ntiles) load_A_tile(smem, sb, abuf ^ 1, tnext, n, tid);
        CP_COMMIT();

        uint32_t aBase = sb + (abuf ? SM_A1 : SM_A0);

        float c[2][8][4];
        #pragma unroll
        for (int mt = 0; mt < 2; mt++)
            #pragma unroll
            for (int nt = 0; nt < 8; nt++)
                #pragma unroll
                for (int j = 0; j < 4; j++) c[mt][nt][j] = 0.0f;

        #pragma unroll
        for (int ks = 0; ks < 8; ks++) {
            uint32_t a[2][4];
            #pragma unroll
            for (int mt = 0; mt < 2; mt++)
                ldsm_x4(aBase + (rowA + mt * 16) * PADB + ks * 32 + colA,
                        a[mt][0], a[mt][1], a[mt][2], a[mt][3]);
            uint32_t b[8][2];
            #pragma unroll
            for (int pr = 0; pr < 4; pr++)
                ldsm_x4(sb + SM_W + (rowB + pr * 16) * PADB + ks * 32 + colB,
                        b[2 * pr][0], b[2 * pr][1], b[2 * pr + 1][0], b[2 * pr + 1][1]);
            #pragma unroll
            for (int mt = 0; mt < 2; mt++)
                #pragma unroll
                for (int nt = 0; nt < 8; nt++)
                    mma_fp16(c[mt][nt], a[mt][0], a[mt][1], a[mt][2], a[mt][3],
                             b[nt][0], b[nt][1]);
        }

        // epilogue: bias + fp16 store (overlaps the in-flight cp.async)
        int blockRow = tile * 128;
        #pragma unroll
        for (int nt = 0; nt < 8; nt++) {
            int col = wc * 64 + nt * 8 + 2 * t4;
            float2 bv = *(const float2*)&bias[col];
            #pragma unroll
            for (int mt = 0; mt < 2; mt++) {
                int row0 = blockRow + wr * 32 + mt * 16 + g;
                if (row0 < n) {
                    __half2 p = __floats2half2_rn(c[mt][nt][0] + bv.x, c[mt][nt][1] + bv.y);
                    *(__half2*)&g_hb[(size_t)row0 * HDIM + col] = p;
                }
                if (row0 + 8 < n) {
                    __half2 p = __floats2half2_rn(c[mt][nt][2] + bv.x, c[mt][nt][3] + bv.y);
                    *(__half2*)&g_hb[(size_t)(row0 + 8) * HDIM + col] = p;
                }
            }
        }

        CP_WAIT_ALL();
        __syncthreads();
        abuf ^= 1;
    }
}

// ---------------- aggregation: half-warp per node, packed edges, 4-wide -----
__global__ __launch_bounds__(256) void k_aggregate(int n) {
    int node = (blockIdx.x * blockDim.x + threadIdx.x) >> 4;
    int hl = threadIdx.x & 15;
    if (node >= n) return;
    int cbase = hl * 8;

    int beg = g_rowptr[node], end = g_rowptr[node + 1];
    float invd = 1.0f / (float)(end - beg + 1);

    float a[8];
    {
        uint4 us = *(const uint4*)&g_hb[(size_t)node * HDIM + cbase];
        float2 t;
        t = __half22float2(*(__half2*)&us.x); a[0] = t.x * invd; a[1] = t.y * invd;
        t = __half22float2(*(__half2*)&us.y); a[2] = t.x * invd; a[3] = t.y * invd;
        t = __half22float2(*(__half2*)&us.z); a[4] = t.x * invd; a[5] = t.y * invd;
        t = __half22float2(*(__half2*)&us.w); a[6] = t.x * invd; a[7] = t.y * invd;
    }

    int p = beg;
    for (; p + 3 < end; p += 4) {
        int2 e0 = g_edge[p],     e1 = g_edge[p + 1];
        int2 e2 = g_edge[p + 2], e3 = g_edge[p + 3];
        uint4 u0 = *(const uint4*)&g_hb[(size_t)e0.x * HDIM + cbase];
        uint4 u1 = *(const uint4*)&g_hb[(size_t)e1.x * HDIM + cbase];
        uint4 u2 = *(const uint4*)&g_hb[(size_t)e2.x * HDIM + cbase];
        uint4 u3 = *(const uint4*)&g_hb[(size_t)e3.x * HDIM + cbase];
        acc8(a, u0, __int_as_float(e0.y));
        acc8(a, u1, __int_as_float(e1.y));
        acc8(a, u2, __int_as_float(e2.y));
        acc8(a, u3, __int_as_float(e3.y));
    }
    for (; p < end; p++) {
        int2 e0 = g_edge[p];
        uint4 u = *(const uint4*)&g_hb[(size_t)e0.x * HDIM + cbase];
        acc8(a, u, __int_as_float(e0.y));
    }

    #pragma unroll
    for (int j = 0; j < 8; j++) a[j] = fmaxf(a[j], 0.0f);

    __half2 p0 = __floats2half2_rn(a[0], a[1]);
    __half2 p1 = __floats2half2_rn(a[2], a[3]);
    __half2 p2 = __floats2half2_rn(a[4], a[5]);
    __half2 p3 = __floats2half2_rn(a[6], a[7]);
    uint4 pk;
    pk.x = *(uint32_t*)&p0; pk.y = *(uint32_t*)&p1;
    pk.z = *(uint32_t*)&p2; pk.w = *(uint32_t*)&p3;
    *(uint4*)&g_xb[(size_t)node * HDIM + cbase] = pk;
}

// ---------------- segment-mean pool (fp16 input) + 2-layer MLP head ---------
__device__ __forceinline__ int lbound(const int* __restrict__ a, int n, int key) {
    int lo = 0, hi = n;
    while (lo < hi) { int m = (lo + hi) >> 1; if (a[m] < key) lo = m + 1; else hi = m; }
    return lo;
}

__global__ __launch_bounds__(128) void k_pool_mlp(const int* __restrict__ batch, int n,
                                                  const float* __restrict__ Wp1,
                                                  const float* __restrict__ bp1,
                                                  const float* __restrict__ Wp2,
                                                  const float* __restrict__ bp2,
                                                  float* __restrict__ out) {
    int g = blockIdx.x;
    int t = threadIdx.x;
    int beg = lbound(batch, n, g);
    int end = lbound(batch, n, g + 1);
    float s = 0.0f;
    for (int r = beg; r < end; r++)
        s += __half2float(g_xb[(size_t)r * HDIM + t]);
    float cnt = (float)(end - beg);
    float inv = 1.0f / fmaxf(cnt, 1.0f);

    __shared__ float ps[HDIM];
    ps[t] = s * inv;
    __syncthreads();

    float hid = bp1[t];
    #pragma unroll
    for (int k = 0; k < HDIM; k++) hid += ps[k] * Wp1[k * HDIM + t];
    hid = fmaxf(hid, 0.0f);

    float term = hid * Wp2[t];
    #pragma unroll
    for (int o = 16; o > 0; o >>= 1) term += __shfl_down_sync(0xFFFFFFFFu, term, o);
    __shared__ float rs[4];
    int lane = t & 31, wid = t >> 5;
    if (lane == 0) rs[wid] = term;
    __syncthreads();
    if (t == 0) out[g] = rs[0] + rs[1] + rs[2] + rs[3] + bp2[0];
}

// ---------------- launch -----------------------------------------------------
extern "C" void kernel_launch(void* const* d_in, const int* in_sizes, int n_in,
                              void* d_out, int out_size) {
    const float* x     = (const float*)d_in[0];
    const int*   ei    = (const int*)d_in[1];
    const int*   batch = (const int*)d_in[2];
    const float* Ws[3] = {(const float*)d_in[3], (const float*)d_in[5], (const float*)d_in[7]};
    const float* bs[3] = {(const float*)d_in[4], (const float*)d_in[6], (const float*)d_in[8]};
    const float* Wp1 = (const float*)d_in[9];
    const float* bp1 = (const float*)d_in[10];
    const float* Wp2 = (const float*)d_in[11];
    const float* bp2 = (const float*)d_in[12];
    float* out = (float*)d_out;

    int n = in_sizes[0] / HDIM;
    int e = in_sizes[1] / 2;
    const int* src = ei;
    const int* dst = ei + e;

    int nb_e = (e + 255) / 256;
    int nscan = (n + 1023) / 1024;

    cudaFuncSetAttribute(k_gemm_pipe, cudaFuncAttributeMaxDynamicSharedMemorySize, SM_TOT);

    __half* Wt0; cudaGetSymbolAddress((void**)&Wt0, g_Wt);
    void* cntPtr; cudaGetSymbolAddress(&cntPtr, g_cnt);
    void* statePtr; cudaGetSymbolAddress(&statePtr, g_state);

    // CSR build (single stream — concurrency contends; memset replaces k_init)
    cudaMemsetAsync(cntPtr, 0, (size_t)n * sizeof(int), 0);
    cudaMemsetAsync(statePtr, 0, (size_t)nscan * sizeof(unsigned), 0);
    k_count<<<nb_e, 256>>>(dst, e);
    k_scan<<<nscan, 1024>>>(n, e);
    k_fill<<<nb_e, 256>>>(src, dst, e);

    // prep: W -> fp16 transposed + x -> fp16 (merged)
    int prep_jobs = 3 * HDIM * HDIM + n * (HDIM / 8);
    k_prep<<<(prep_jobs + 255) / 256, 256>>>(Ws[0], Ws[1], Ws[2], x, n);

    int ntiles = (n + 127) / 128;
    int gsz = 296;                       // 2 CTAs/SM x 148 SMs
    if (gsz > ntiles) gsz = ntiles;
    int agg_blocks = (n + 15) / 16;

    for (int l = 0; l < 3; l++) {
        k_gemm_pipe<<<gsz, 256, SM_TOT>>>(Wt0 + l * HDIM * HDIM, bs[l], n, ntiles, gsz);
        k_aggregate<<<agg_blocks, 256>>>(n);
    }

    // pool + MLP head
    k_pool_mlp<<<out_size, 128>>>(batch, n, Wp1, bp1, Wp2, bp2, out);
}

// round 16
// speedup vs baseline: 1.0485x; 1.0485x over previous
#include <cuda_runtime.h>
#include <cuda_fp16.h>
#include <cstdint>

// Problem constants (fixed by the dataset)
#define MAXN 100000
#define MAXE 1600000
#define HDIM 128
#define NSCAN_BLOCKS ((MAXN + 1023) / 1024)

// ---------------- scratch (device globals; no runtime allocation) ----------
__device__ int   g_cnt[MAXN];
__device__ int   g_rowptr[MAXN + 1];
__device__ int2  g_edge[MAXE];          // packed (src, nrm-as-int) per edge
__device__ int   g_bsum[NSCAN_BLOCKS + 1];
__device__ __half g_hb[(size_t)MAXN * HDIM];  // post-GEMM features (fp16)
__device__ __half g_xb[(size_t)MAXN * HDIM];  // aggregate out / GEMM in (fp16)
__device__ __half g_Wt[3 * HDIM * HDIM];      // W^T [n][k] fp16

// ---------------- helpers ----------------------------------------------------
__device__ __forceinline__ uint32_t smem_to_u32(const void* p) {
    uint32_t a;
    asm("{ .reg .u64 t; cvta.to.shared.u64 t, %1; cvt.u32.u64 %0, t; }"
        : "=r"(a) : "l"(p));
    return a;
}

__device__ __forceinline__ void ldsm_x4(uint32_t addr, uint32_t& r0, uint32_t& r1,
                                        uint32_t& r2, uint32_t& r3) {
    asm volatile("ldmatrix.sync.aligned.m8n8.x4.shared.b16 {%0,%1,%2,%3}, [%4];"
                 : "=r"(r0), "=r"(r1), "=r"(r2), "=r"(r3) : "r"(addr));
}

__device__ __forceinline__ void mma_fp16(float* c, uint32_t a0, uint32_t a1,
                                         uint32_t a2, uint32_t a3,
                                         uint32_t b0, uint32_t b1) {
    asm volatile(
        "mma.sync.aligned.m16n8k16.row.col.f32.f16.f16.f32 "
        "{%0,%1,%2,%3}, {%4,%5,%6,%7}, {%8,%9}, {%0,%1,%2,%3};"
        : "+f"(c[0]), "+f"(c[1]), "+f"(c[2]), "+f"(c[3])
        : "r"(a0), "r"(a1), "r"(a2), "r"(a3), "r"(b0), "r"(b1));
}

__device__ __forceinline__ void cp_async16(uint32_t smem_addr, const void* gptr) {
    asm volatile("cp.async.cg.shared.global [%0], [%1], 16;"
                 :: "r"(smem_addr), "l"(gptr));
}
#define CP_COMMIT()   asm volatile("cp.async.commit_group;" ::: "memory")
#define CP_WAIT_ALL() asm volatile("cp.async.wait_group 0;" ::: "memory")

__device__ __forceinline__ void acc8(float* a, uint4 u, float w) {
    float2 t;
    t = __half22float2(*(__half2*)&u.x); a[0] += t.x * w; a[1] += t.y * w;
    t = __half22float2(*(__half2*)&u.y); a[2] += t.x * w; a[3] += t.y * w;
    t = __half22float2(*(__half2*)&u.z); a[4] += t.x * w; a[5] += t.y * w;
    t = __half22float2(*(__half2*)&u.w); a[6] += t.x * w; a[7] += t.y * w;
}

// ---------------- CSR build -------------------------------------------------
__global__ void k_count(const int* __restrict__ dst, int e) {
    int i = blockIdx.x * blockDim.x + threadIdx.x;
    if (i < e) atomicAdd(&g_cnt[dst[i]], 1);
}

__global__ void k_scan1(int n) {
    int i = blockIdx.x * 1024 + threadIdx.x;
    int v = (i < n) ? g_cnt[i] : 0;
    int lane = threadIdx.x & 31, wid = threadIdx.x >> 5;
    int x = v;
    #pragma unroll
    for (int o = 1; o < 32; o <<= 1) {
        int y = __shfl_up_sync(0xFFFFFFFFu, x, o);
        if (lane >= o) x += y;
    }
    __shared__ int ws[32];
    if (lane == 31) ws[wid] = x;
    __syncthreads();
    if (wid == 0) {
        int w = ws[lane];
        #pragma unroll
        for (int o = 1; o < 32; o <<= 1) {
            int y = __shfl_up_sync(0xFFFFFFFFu, w, o);
            if (lane >= o) w += y;
        }
        ws[lane] = w;
    }
    __syncthreads();
    int prefix = (wid > 0) ? ws[wid - 1] : 0;
    int incl = x + prefix;
    if (i < n) g_rowptr[i] = incl - v;
    if (threadIdx.x == 1023) g_bsum[blockIdx.x] = incl;
}

// parallel 128-thread exclusive scan of block sums (nb <= 128)
__global__ void k_scan2(int nb) {
    int t = threadIdx.x;
    int lane = t & 31, wid = t >> 5;
    int v = (t < nb) ? g_bsum[t] : 0;
    int x = v;
    #pragma unroll
    for (int o = 1; o < 32; o <<= 1) {
        int y = __shfl_up_sync(0xFFFFFFFFu, x, o);
        if (lane >= o) x += y;
    }
    __shared__ int ws[4];
    if (lane == 31) ws[wid] = x;
    __syncthreads();
    int prefix = 0;
    #pragma unroll
    for (int w = 0; w < 4; w++) prefix += (w < wid) ? ws[w] : 0;
    if (t < nb) g_bsum[t] = x + prefix - v;   // exclusive
}

__global__ void k_scan3(int n, int e) {
    int i = blockIdx.x * blockDim.x + threadIdx.x;
    if (i < n) g_rowptr[i] += g_bsum[i >> 10];
    if (i == 0) g_rowptr[n] = e;
}

// countdown-cursor fill; degree from rowptr diffs (+1 self-loop)
__global__ void k_fill(const int* __restrict__ src, const int* __restrict__ dst, int e) {
    int i = blockIdx.x * blockDim.x + threadIdx.x;
    if (i >= e) return;
    int d = dst[i], s = src[i];
    int rpd1 = g_rowptr[d + 1];
    int c = atomicAdd(&g_cnt[d], -1);
    int p = rpd1 - c;
    float degd = (float)(rpd1 - g_rowptr[d] + 1);
    float degs = (float)(g_rowptr[s + 1] - g_rowptr[s] + 1);
    float nrm = rsqrtf(degs * degd);
    g_edge[p] = make_int2(s, __float_as_int(nrm));
}

// ---------------- prep: W -> fp16 transposed AND x -> fp16 (merged) ---------
__global__ void k_prep(const float* __restrict__ W0, const float* __restrict__ W1,
                       const float* __restrict__ W2, const float* __restrict__ x,
                       int n) {
    int i = blockIdx.x * blockDim.x + threadIdx.x;
    const int WJOBS = 3 * HDIM * HDIM;
    if (i < WJOBS) {
        int l = i / (HDIM * HDIM);
        int r = i % (HDIM * HDIM);
        int nn = r / HDIM, kk = r % HDIM;
        const float* W = (l == 0) ? W0 : (l == 1) ? W1 : W2;
        g_Wt[l * HDIM * HDIM + nn * HDIM + kk] = __float2half_rn(W[kk * HDIM + nn]);
        return;
    }
    int j = i - WJOBS;                      // 8 x elements per job
    if (j >= n * (HDIM / 8)) return;
    const float4* p = (const float4*)x + (size_t)j * 2;
    float4 v0 = p[0], v1 = p[1];
    __half2 a = __floats2half2_rn(v0.x, v0.y);
    __half2 b = __floats2half2_rn(v0.z, v0.w);
    __half2 c = __floats2half2_rn(v1.x, v1.y);
    __half2 d = __floats2half2_rn(v1.z, v1.w);
    uint4 o;
    o.x = *(uint32_t*)&a; o.y = *(uint32_t*)&b;
    o.z = *(uint32_t*)&c; o.w = *(uint32_t*)&d;
    *((uint4*)g_xb + j) = o;
}

// ---------------- pipelined GEMM: Hb = Xb @ W + b ---------------------------
#define PADB 272
#define SM_W   0
#define SM_A0  (128 * PADB)
#define SM_A1  (2 * 128 * PADB)
#define SM_TOT (3 * 128 * PADB)   // 104448 -> 2 CTAs/SM

__device__ __forceinline__ void load_A_tile(char* smem, uint32_t sb, int abuf,
                                            int tile, int n, int tid) {
    uint32_t base = abuf ? SM_A1 : SM_A0;
    #pragma unroll
    for (int i = 0; i < 8; i++) {
        int gi = tid + i * 256;
        int r = gi >> 4, c16 = gi & 15;
        int row = tile * 128 + r;
        uint32_t dst = sb + base + r * PADB + c16 * 16;
        if (row < n) {
            cp_async16(dst, &g_xb[(size_t)row * HDIM + c16 * 8]);
        } else {
            *(uint4*)(smem + base + r * PADB + c16 * 16) = make_uint4(0, 0, 0, 0);
        }
    }
}

__global__ __launch_bounds__(256, 2) void k_gemm_pipe(
    const __half* __restrict__ Wt,
    const float* __restrict__ bias,
    int n, int ntiles, int gsz)
{
    extern __shared__ __align__(16) char smem[];
    uint32_t sb = smem_to_u32(smem);
    int tid = threadIdx.x;
    int lane = tid & 31, wid = tid >> 5;
    int wr = wid & 3;
    int wc = wid >> 2;

    int t0 = blockIdx.x;
    if (t0 >= ntiles) return;

    // prologue: W + first A tile via cp.async
    #pragma unroll
    for (int i = 0; i < 8; i++) {
        int gi = tid + i * 256;
        int r = gi >> 4, c16 = gi & 15;
        cp_async16(sb + SM_W + r * PADB + c16 * 16, &Wt[(size_t)r * HDIM + c16 * 8]);
    }
    load_A_tile(smem, sb, 0, t0, n, tid);
    CP_COMMIT();
    CP_WAIT_ALL();
    __syncthreads();

    int q = lane >> 3, rl = lane & 7;
    int rowA = wr * 32 + (q & 1) * 8 + rl;
    int colA = (q >> 1) * 16;
    int rowB = wc * 64 + (q >> 1) * 8 + rl;
    int colB = (q & 1) * 16;
    int g = lane >> 2, t4 = lane & 3;

    int abuf = 0;
    for (int tile = t0; tile < ntiles; tile += gsz) {
        int tnext = tile + gsz;
        if (tnext < ntiles) load_A_tile(smem, sb, abuf ^ 1, tnext, n, tid);
        CP_COMMIT();

        uint32_t aBase = sb + (abuf ? SM_A1 : SM_A0);

        float c[2][8][4];
        #pragma unroll
        for (int mt = 0; mt < 2; mt++)
            #pragma unroll
            for (int nt = 0; nt < 8; nt++)
                #pragma unroll
                for (int j = 0; j < 4; j++) c[mt][nt][j] = 0.0f;

        #pragma unroll
        for (int ks = 0; ks < 8; ks++) {
            uint32_t a[2][4];
            #pragma unroll
            for (int mt = 0; mt < 2; mt++)
                ldsm_x4(aBase + (rowA + mt * 16) * PADB + ks * 32 + colA,
                        a[mt][0], a[mt][1], a[mt][2], a[mt][3]);
            uint32_t b[8][2];
            #pragma unroll
            for (int pr = 0; pr < 4; pr++)
                ldsm_x4(sb + SM_W + (rowB + pr * 16) * PADB + ks * 32 + colB,
                        b[2 * pr][0], b[2 * pr][1], b[2 * pr + 1][0], b[2 * pr + 1][1]);
            #pragma unroll
            for (int mt = 0; mt < 2; mt++)
                #pragma unroll
                for (int nt = 0; nt < 8; nt++)
                    mma_fp16(c[mt][nt], a[mt][0], a[mt][1], a[mt][2], a[mt][3],
                             b[nt][0], b[nt][1]);
        }

        // epilogue: bias + fp16 store (overlaps the in-flight cp.async)
        int blockRow = tile * 128;
        #pragma unroll
        for (int nt = 0; nt < 8; nt++) {
            int col = wc * 64 + nt * 8 + 2 * t4;
            float2 bv = *(const float2*)&bias[col];
            #pragma unroll
            for (int mt = 0; mt < 2; mt++) {
                int row0 = blockRow + wr * 32 + mt * 16 + g;
                if (row0 < n) {
                    __half2 p = __floats2half2_rn(c[mt][nt][0] + bv.x, c[mt][nt][1] + bv.y);
                    *(__half2*)&g_hb[(size_t)row0 * HDIM + col] = p;
                }
                if (row0 + 8 < n) {
                    __half2 p = __floats2half2_rn(c[mt][nt][2] + bv.x, c[mt][nt][3] + bv.y);
                    *(__half2*)&g_hb[(size_t)(row0 + 8) * HDIM + col] = p;
                }
            }
        }

        CP_WAIT_ALL();
        __syncthreads();
        abuf ^= 1;
    }
}

// ---------------- aggregation: half-warp per node, packed edges, 4-wide -----
__global__ __launch_bounds__(256) void k_aggregate(int n) {
    int node = (blockIdx.x * blockDim.x + threadIdx.x) >> 4;
    int hl = threadIdx.x & 15;
    if (node >= n) return;
    int cbase = hl * 8;

    int beg = g_rowptr[node], end = g_rowptr[node + 1];
    float invd = 1.0f / (float)(end - beg + 1);

    float a[8];
    {
        uint4 us = *(const uint4*)&g_hb[(size_t)node * HDIM + cbase];
        float2 t;
        t = __half22float2(*(__half2*)&us.x); a[0] = t.x * invd; a[1] = t.y * invd;
        t = __half22float2(*(__half2*)&us.y); a[2] = t.x * invd; a[3] = t.y * invd;
        t = __half22float2(*(__half2*)&us.z); a[4] = t.x * invd; a[5] = t.y * invd;
        t = __half22float2(*(__half2*)&us.w); a[6] = t.x * invd; a[7] = t.y * invd;
    }

    int p = beg;
    for (; p + 3 < end; p += 4) {
        int2 e0 = g_edge[p],     e1 = g_edge[p + 1];
        int2 e2 = g_edge[p + 2], e3 = g_edge[p + 3];
        uint4 u0 = *(const uint4*)&g_hb[(size_t)e0.x * HDIM + cbase];
        uint4 u1 = *(const uint4*)&g_hb[(size_t)e1.x * HDIM + cbase];
        uint4 u2 = *(const uint4*)&g_hb[(size_t)e2.x * HDIM + cbase];
        uint4 u3 = *(const uint4*)&g_hb[(size_t)e3.x * HDIM + cbase];
        acc8(a, u0, __int_as_float(e0.y));
        acc8(a, u1, __int_as_float(e1.y));
        acc8(a, u2, __int_as_float(e2.y));
        acc8(a, u3, __int_as_float(e3.y));
    }
    for (; p < end; p++) {
        int2 e0 = g_edge[p];
        uint4 u = *(const uint4*)&g_hb[(size_t)e0.x * HDIM + cbase];
        acc8(a, u, __int_as_float(e0.y));
    }

    #pragma unroll
    for (int j = 0; j < 8; j++) a[j] = fmaxf(a[j], 0.0f);

    __half2 p0 = __floats2half2_rn(a[0], a[1]);
    __half2 p1 = __floats2half2_rn(a[2], a[3]);
    __half2 p2 = __floats2half2_rn(a[4], a[5]);
    __half2 p3 = __floats2half2_rn(a[6], a[7]);
    uint4 pk;
    pk.x = *(uint32_t*)&p0; pk.y = *(uint32_t*)&p1;
    pk.z = *(uint32_t*)&p2; pk.w = *(uint32_t*)&p3;
    *(uint4*)&g_xb[(size_t)node * HDIM + cbase] = pk;
}

// ---------------- segment-mean pool (fp16 input) + 2-layer MLP head ---------
__device__ __forceinline__ int lbound(const int* __restrict__ a, int n, int key) {
    int lo = 0, hi = n;
    while (lo < hi) { int m = (lo + hi) >> 1; if (a[m] < key) lo = m + 1; else hi = m; }
    return lo;
}

__global__ __launch_bounds__(128) void k_pool_mlp(const int* __restrict__ batch, int n,
                                                  const float* __restrict__ Wp1,
                                                  const float* __restrict__ bp1,
                                                  const float* __restrict__ Wp2,
                                                  const float* __restrict__ bp2,
                                                  float* __restrict__ out) {
    int g = blockIdx.x;
    int t = threadIdx.x;
    int beg = lbound(batch, n, g);
    int end = lbound(batch, n, g + 1);
    float s = 0.0f;
    for (int r = beg; r < end; r++)
        s += __half2float(g_xb[(size_t)r * HDIM + t]);
    float cnt = (float)(end - beg);
    float inv = 1.0f / fmaxf(cnt, 1.0f);

    __shared__ float ps[HDIM];
    ps[t] = s * inv;
    __syncthreads();

    float hid = bp1[t];
    #pragma unroll
    for (int k = 0; k < HDIM; k++) hid += ps[k] * Wp1[k * HDIM + t];
    hid = fmaxf(hid, 0.0f);

    float term = hid * Wp2[t];
    #pragma unroll
    for (int o = 16; o > 0; o >>= 1) term += __shfl_down_sync(0xFFFFFFFFu, term, o);
    __shared__ float rs[4];
    int lane = t & 31, wid = t >> 5;
    if (lane == 0) rs[wid] = term;
    __syncthreads();
    if (t == 0) out[g] = rs[0] + rs[1] + rs[2] + rs[3] + bp2[0];
}

// ---------------- launch -----------------------------------------------------
extern "C" void kernel_launch(void* const* d_in, const int* in_sizes, int n_in,
                              void* d_out, int out_size) {
    const float* x     = (const float*)d_in[0];
    const int*   ei    = (const int*)d_in[1];
    const int*   batch = (const int*)d_in[2];
    const float* Ws[3] = {(const float*)d_in[3], (const float*)d_in[5], (const float*)d_in[7]};
    const float* bs[3] = {(const float*)d_in[4], (const float*)d_in[6], (const float*)d_in[8]};
    const float* Wp1 = (const float*)d_in[9];
    const float* bp1 = (const float*)d_in[10];
    const float* Wp2 = (const float*)d_in[11];
    const float* bp2 = (const float*)d_in[12];
    float* out = (float*)d_out;

    int n = in_sizes[0] / HDIM;
    int e = in_sizes[1] / 2;
    const int* src = ei;
    const int* dst = ei + e;

    int nb_n = (n + 255) / 256;
    int nb_e = (e + 255) / 256;
    int nscan = (n + 1023) / 1024;

    cudaFuncSetAttribute(k_gemm_pipe, cudaFuncAttributeMaxDynamicSharedMemorySize, SM_TOT);

    __half* Wt0; cudaGetSymbolAddress((void**)&Wt0, g_Wt);
    void* cntPtr; cudaGetSymbolAddress(&cntPtr, g_cnt);

    // CSR build (single stream; memset replaces k_init; proven 3-stage scan)
    cudaMemsetAsync(cntPtr, 0, (size_t)n * sizeof(int), 0);
    k_count<<<nb_e, 256>>>(dst, e);
    k_scan1<<<nscan, 1024>>>(n);
    k_scan2<<<1, 128>>>(nscan);
    k_scan3<<<nb_n, 256>>>(n, e);
    k_fill<<<nb_e, 256>>>(src, dst, e);

    // prep: W -> fp16 transposed + x -> fp16 (merged)
    int prep_jobs = 3 * HDIM * HDIM + n * (HDIM / 8);
    k_prep<<<(prep_jobs + 255) / 256, 256>>>(Ws[0], Ws[1], Ws[2], x, n);

    int ntiles = (n + 127) / 128;
    int gsz = 296;                       // 2 CTAs/SM x 148 SMs
    if (gsz > ntiles) gsz = ntiles;
    int agg_blocks = (n + 15) / 16;

    for (int l = 0; l < 3; l++) {
        k_gemm_pipe<<<gsz, 256, SM_TOT>>>(Wt0 + l * HDIM * HDIM, bs[l], n, ntiles, gsz);
        k_aggregate<<<agg_blocks, 256>>>(n);
    }

    // pool + MLP head
    k_pool_mlp<<<out_size, 128>>>(batch, n, Wp1, bp1, Wp2, bp2, out);
}